// round 10
// baseline (speedup 1.0000x reference)
#include <cuda_runtime.h>
#include <cuda_bf16.h>
#include <math.h>

// ---------------------------------------------------------------------------
// RawSequenceEncoder: compress -> in-proj -> 4x conv blocks -> final LN
// B=32, S=4096, D=256, T=256, NB=4, K=5. M = 8192 rows.
// GEMMs: warp-level mma.sync bf16, 2-term bf16 split (hh+hl+lh), fp32 acc.
// R10: tile 64x128 (grid 2x larger -> fixes occ=14.5%/grid-starvation seen in
// R9 profile), 3-stage cp.async ring with ONE barrier per k-iter.
// ---------------------------------------------------------------------------

#define BATCH 32
#define SEQ   4096
#define DMODEL 256
#define TLEN  256
#define NBLK  4
#define KSZ   5
#define MROWS (BATCH * TLEN)   // 8192
#define EPSV  1e-5f
#define KDIM  256

// ------------------------- scratch (static, no allocs) ---------------------
static __device__ __nv_bfloat16 g_ahi[MROWS * KDIM];
static __device__ __nv_bfloat16 g_alo[MROWS * KDIM];
static __device__ __nv_bfloat16 g_chi[MROWS * KDIM];
static __device__ __nv_bfloat16 g_clo[MROWS * KDIM];
#define WOFF_IN    0
#define WOFF_WOUT(i) (65536 + (i) * 65536)
#define WOFF_GATE(i) (65536 * 5 + (i) * 131072)
#define WTOT (65536 * 5 + 131072 * 4)
static __device__ __nv_bfloat16 g_whi[WTOT];
static __device__ __nv_bfloat16 g_wlo[WTOT];
static __device__ float g_h[MROWS * DMODEL];
static __device__ int   g_len[BATCH];

// ------------------------- PTX helpers (sm_80-era only) ---------------------
__device__ __forceinline__ unsigned smem_u32(const void* p) {
    unsigned a;
    asm("{ .reg .u64 t; cvta.to.shared.u64 t, %1; cvt.u32.u64 %0, t; }"
        : "=r"(a) : "l"(p));
    return a;
}
#define CP_ASYNC16(dst, src) \
    asm volatile("cp.async.cg.shared.global [%0], [%1], 16;" :: "r"(dst), "l"(src))
#define CP_COMMIT() asm volatile("cp.async.commit_group;" ::: "memory")
#define CP_WAIT(N)  asm volatile("cp.async.wait_group %0;" :: "n"(N) : "memory")

__device__ __forceinline__ void ldsm_x4(unsigned* r, unsigned addr) {
    asm volatile("ldmatrix.sync.aligned.m8n8.x4.shared.b16 {%0,%1,%2,%3}, [%4];"
                 : "=r"(r[0]), "=r"(r[1]), "=r"(r[2]), "=r"(r[3]) : "r"(addr));
}
__device__ __forceinline__ void ldsm_x2(unsigned* r, unsigned addr) {
    asm volatile("ldmatrix.sync.aligned.m8n8.x2.shared.b16 {%0,%1}, [%2];"
                 : "=r"(r[0]), "=r"(r[1]) : "r"(addr));
}
__device__ __forceinline__ void mma16816(float* d, const unsigned* a, const unsigned* b) {
    asm volatile("mma.sync.aligned.m16n8k16.row.col.f32.bf16.bf16.f32 "
                 "{%0,%1,%2,%3}, {%4,%5,%6,%7}, {%8,%9}, {%0,%1,%2,%3};"
                 : "+f"(d[0]), "+f"(d[1]), "+f"(d[2]), "+f"(d[3])
                 : "r"(a[0]), "r"(a[1]), "r"(a[2]), "r"(a[3]),
                   "r"(b[0]), "r"(b[1]));
}

__device__ __forceinline__ void splitf(float x, __nv_bfloat16& h, __nv_bfloat16& l) {
    h = __float2bfloat16_rn(x);
    l = __float2bfloat16_rn(x - __bfloat162float(h));
}

// ------------------------- fused mask detect + lengths ----------------------
__global__ __launch_bounds__(256)
void lengths_kernel(const unsigned char* __restrict__ maskp) {
    __shared__ float sh[8];
    __shared__ int sflags;   // bit0 = saw byte>1 (f32), bit1 = nonzero at i%4!=0 (u8)
    int b = blockIdx.x;
    if (threadIdx.x == 0) sflags = 0;
    __syncthreads();

    const unsigned* pw = (const unsigned*)maskp;
    const int nwords = (BATCH * SEQ) / 4;   // safe lower bound across dtypes
    int fl = 0;
    for (int i = threadIdx.x; i < nwords; i += 256) {
        unsigned w = pw[i];
        unsigned b0 = w & 0xFF, b1 = (w >> 8) & 0xFF,
                 b2 = (w >> 16) & 0xFF, b3 = w >> 24;
        if (b0 > 1 || b1 > 1 || b2 > 1 || b3 > 1) fl |= 1;
        if (w & 0xFFFFFF00u) fl |= 2;
    }
    if (__any_sync(0xffffffffu, fl & 1)) fl |= 1;
    if (__any_sync(0xffffffffu, fl & 2)) fl |= 2;
    if ((threadIdx.x & 31) == 0 && fl) atomicOr(&sflags, fl);
    __syncthreads();
    int kind = (sflags & 1) ? 2 : ((sflags & 2) ? 0 : 1); // 2=f32, 0=u8, 1=i32

    float local = 0.0f;
    if (kind == 0) {
        const unsigned char* p = maskp + (size_t)b * SEQ;
        for (int i = threadIdx.x; i < SEQ; i += 256) local += (float)p[i];
    } else if (kind == 1) {
        const int* p = (const int*)maskp + (size_t)b * SEQ;
        for (int i = threadIdx.x; i < SEQ; i += 256) local += (float)p[i];
    } else {
        const float* p = (const float*)maskp + (size_t)b * SEQ;
        for (int i = threadIdx.x; i < SEQ; i += 256) local += p[i];
    }
    int lane = threadIdx.x & 31, w = threadIdx.x >> 5;
    #pragma unroll
    for (int o = 16; o > 0; o >>= 1) local += __shfl_down_sync(0xffffffffu, local, o);
    if (lane == 0) sh[w] = local;
    __syncthreads();
    if (threadIdx.x == 0) {
        float tot = 0.0f;
        #pragma unroll
        for (int i = 0; i < 8; i++) tot += sh[i];
        g_len[b] = (int)lrintf(tot);
    }
}

// ------------------------- compress -> bf16 hi/lo ----------------------------
__global__ void compress_kernel(const float* __restrict__ x) {
    int b = blockIdx.y;
    int t = blockIdx.x * 2 + (threadIdx.x >> 6);
    int lane = threadIdx.x & 63;
    int L = g_len[b];
    float Lf  = (float)L;
    float src = ((float)t + 0.5f) * (Lf * (1.0f / (float)TLEN)) - 0.5f;
    float hi  = fmaxf(Lf - 1.0f, 0.0f);
    src = fminf(fmaxf(src, 0.0f), hi);
    int   i0 = (int)floorf(src);
    int   i1 = min(i0 + 1, max(L - 1, 0));
    float w  = src - (float)i0;
    const float4* r0 = (const float4*)(x + ((size_t)b * SEQ + i0) * DMODEL);
    const float4* r1 = (const float4*)(x + ((size_t)b * SEQ + i1) * DMODEL);
    float4 v0 = r0[lane], v1 = r1[lane];
    float o[4];
    o[0] = (1.0f - w) * v0.x + w * v1.x;
    o[1] = (1.0f - w) * v0.y + w * v1.y;
    o[2] = (1.0f - w) * v0.z + w * v1.z;
    o[3] = (1.0f - w) * v0.w + w * v1.w;
    size_t base = ((size_t)(b * TLEN + t)) * DMODEL + lane * 4;
    __nv_bfloat16 h0, l0, h1, l1;
    splitf(o[0], h0, l0); splitf(o[1], h1, l1);
    __nv_bfloat162 ph0; ph0.x = h0; ph0.y = h1;
    __nv_bfloat162 pl0; pl0.x = l0; pl0.y = l1;
    splitf(o[2], h0, l0); splitf(o[3], h1, l1);
    __nv_bfloat162 ph1; ph1.x = h0; ph1.y = h1;
    __nv_bfloat162 pl1; pl1.x = l0; pl1.y = l1;
    *(__nv_bfloat162*)(g_ahi + base)     = ph0;
    *(__nv_bfloat162*)(g_ahi + base + 2) = ph1;
    *(__nv_bfloat162*)(g_alo + base)     = pl0;
    *(__nv_bfloat162*)(g_alo + base + 2) = pl1;
}

// ------------------------- fused weight prep (ONE launch) -------------------
__global__ void prep_all_w_kernel(const float* __restrict__ in_w,
                                  const float* __restrict__ wout_w,
                                  const float* __restrict__ win_w,
                                  __nv_bfloat16* __restrict__ hi,
                                  __nv_bfloat16* __restrict__ lo) {
    __shared__ float t[32][33];
    int bid = blockIdx.x;
    const float* W;
    int srcld, gated, tile;
    size_t dsto;
    if (bid < 64) {
        W = in_w; srcld = 256; gated = 0; dsto = WOFF_IN; tile = bid;
    } else if (bid < 320) {
        int tt = bid - 64, i = tt >> 6;
        W = wout_w + (size_t)i * 65536; srcld = 256; gated = 0;
        dsto = WOFF_WOUT(i); tile = tt & 63;
    } else {
        int tt = bid - 320, i = tt >> 7;
        W = win_w + (size_t)i * 131072; srcld = 512; gated = 1;
        dsto = WOFF_GATE(i); tile = tt & 127;
    }
    int kx = (tile & 7) * 32, py = (tile >> 3) * 32;
    int tx = threadIdx.x, ty = threadIdx.y;
    int p = py + tx;
    int srccol;
    if (gated) {
        int j = p >> 7, r5 = p & 127;
        srccol = j * 64 + (r5 & 63) + ((r5 & 64) ? 256 : 0);
    } else srccol = p;
    t[ty][tx] = W[(size_t)(kx + ty) * srcld + srccol];
    __syncthreads();
    int pp = py + ty, k = kx + tx;
    __nv_bfloat16 h, l;
    splitf(t[tx][ty], h, l);
    hi[dsto + (size_t)pp * KDIM + k] = h;
    lo[dsto + (size_t)pp * KDIM + k] = l;
}

// ------------------------- fused LN + conv -> bf16 hi/lo --------------------
__global__ __launch_bounds__(256)
void lnconv_kernel(const float* __restrict__ h,
                   const float* __restrict__ g, const float* __restrict__ bta,
                   const float* __restrict__ w, const float* __restrict__ cbias,
                   __nv_bfloat16* __restrict__ ohi, __nv_bfloat16* __restrict__ olo) {
    __shared__ float sh[36][DMODEL];
    int b = blockIdx.y;
    int t0 = blockIdx.x * 32;
    int warp = threadIdx.x >> 5, lane = threadIdx.x & 31;

    for (int r = warp; r < 36; r += 8) {
        int t = t0 - 2 + r;
        if (t < 0 || t >= TLEN) {
            float4 z = make_float4(0.f, 0.f, 0.f, 0.f);
            ((float4*)sh[r])[lane * 2]     = z;
            ((float4*)sh[r])[lane * 2 + 1] = z;
        } else {
            const float4* p = (const float4*)(h + ((size_t)(b * TLEN + t)) * DMODEL);
            float4 v0 = p[lane * 2], v1 = p[lane * 2 + 1];
            float s  = v0.x + v0.y + v0.z + v0.w + v1.x + v1.y + v1.z + v1.w;
            float sq = v0.x*v0.x + v0.y*v0.y + v0.z*v0.z + v0.w*v0.w
                     + v1.x*v1.x + v1.y*v1.y + v1.z*v1.z + v1.w*v1.w;
            #pragma unroll
            for (int o = 16; o > 0; o >>= 1) {
                s  += __shfl_xor_sync(0xffffffffu, s,  o);
                sq += __shfl_xor_sync(0xffffffffu, sq, o);
            }
            float mu  = s  * (1.0f / (float)DMODEL);
            float var = sq * (1.0f / (float)DMODEL) - mu * mu;
            float rs  = rsqrtf(var + EPSV);
            const float4* gp = (const float4*)g;
            const float4* bp = (const float4*)bta;
            float4 g0 = gp[lane * 2], g1 = gp[lane * 2 + 1];
            float4 b0 = bp[lane * 2], b1 = bp[lane * 2 + 1];
            float4 o0, o1;
            o0.x = (v0.x - mu) * rs * g0.x + b0.x;
            o0.y = (v0.y - mu) * rs * g0.y + b0.y;
            o0.z = (v0.z - mu) * rs * g0.z + b0.z;
            o0.w = (v0.w - mu) * rs * g0.w + b0.w;
            o1.x = (v1.x - mu) * rs * g1.x + b1.x;
            o1.y = (v1.y - mu) * rs * g1.y + b1.y;
            o1.z = (v1.z - mu) * rs * g1.z + b1.z;
            o1.w = (v1.w - mu) * rs * g1.w + b1.w;
            ((float4*)sh[r])[lane * 2]     = o0;
            ((float4*)sh[r])[lane * 2 + 1] = o1;
        }
    }
    __syncthreads();

    int d = threadIdx.x;
    float w0 = w[d * KSZ + 0], w1 = w[d * KSZ + 1], w2 = w[d * KSZ + 2];
    float w3 = w[d * KSZ + 3], w4 = w[d * KSZ + 4];
    float cb = cbias[d];
    float acc[32];
    #pragma unroll
    for (int t = 0; t < 32; t++) {
        float a = cb;
        a = fmaf(w0, sh[t    ][d], a);
        a = fmaf(w1, sh[t + 1][d], a);
        a = fmaf(w2, sh[t + 2][d], a);
        a = fmaf(w3, sh[t + 3][d], a);
        a = fmaf(w4, sh[t + 4][d], a);
        acc[t] = a;
    }
    __syncthreads();
    #pragma unroll
    for (int t = 0; t < 32; t++) sh[t][d] = acc[t];
    __syncthreads();

    size_t rowbase = (size_t)(b * TLEN + t0);
    for (int p = threadIdx.x; p < 32 * 128; p += 256) {
        int r = p >> 7, dp = (p & 127) * 2;
        __nv_bfloat16 h0, l0, h1, l1;
        splitf(sh[r][dp],     h0, l0);
        splitf(sh[r][dp + 1], h1, l1);
        __nv_bfloat162 ph; ph.x = h0; ph.y = h1;
        __nv_bfloat162 pl; pl.x = l0; pl.y = l1;
        *(__nv_bfloat162*)(ohi + (rowbase + r) * DMODEL + dp) = ph;
        *(__nv_bfloat162*)(olo + (rowbase + r) * DMODEL + dp) = pl;
    }
}

// ------------------------- warp-per-row final layer norm --------------------
__global__ void ln_warp_kernel(const float* __restrict__ in,
                               const float* __restrict__ g,
                               const float* __restrict__ bta,
                               float* __restrict__ out) {
    int warp = threadIdx.x >> 5, lane = threadIdx.x & 31;
    int m = blockIdx.x * 8 + warp;
    const float4* p = (const float4*)(in + (size_t)m * DMODEL);
    float4 v0 = p[lane * 2], v1 = p[lane * 2 + 1];
    float s  = v0.x + v0.y + v0.z + v0.w + v1.x + v1.y + v1.z + v1.w;
    float sq = v0.x*v0.x + v0.y*v0.y + v0.z*v0.z + v0.w*v0.w
             + v1.x*v1.x + v1.y*v1.y + v1.z*v1.z + v1.w*v1.w;
    #pragma unroll
    for (int o = 16; o > 0; o >>= 1) {
        s  += __shfl_xor_sync(0xffffffffu, s,  o);
        sq += __shfl_xor_sync(0xffffffffu, sq, o);
    }
    float mu  = s  * (1.0f / (float)DMODEL);
    float var = sq * (1.0f / (float)DMODEL) - mu * mu;
    float rs  = rsqrtf(var + EPSV);
    const float4* gp = (const float4*)g;
    const float4* bp = (const float4*)bta;
    float4 g0 = gp[lane * 2], g1 = gp[lane * 2 + 1];
    float4 b0 = bp[lane * 2], b1 = bp[lane * 2 + 1];
    float4 o0, o1;
    o0.x = (v0.x - mu) * rs * g0.x + b0.x;
    o0.y = (v0.y - mu) * rs * g0.y + b0.y;
    o0.z = (v0.z - mu) * rs * g0.z + b0.z;
    o0.w = (v0.w - mu) * rs * g0.w + b0.w;
    o1.x = (v1.x - mu) * rs * g1.x + b1.x;
    o1.y = (v1.y - mu) * rs * g1.y + b1.y;
    o1.z = (v1.z - mu) * rs * g1.z + b1.z;
    o1.w = (v1.w - mu) * rs * g1.w + b1.w;
    ((float4*)(out + (size_t)m * DMODEL))[lane * 2]     = o0;
    ((float4*)(out + (size_t)m * DMODEL))[lane * 2 + 1] = o1;
}

// ------------------------- mma.sync GEMM (64x128 tile, 3-stage ring) --------
// Per CTA: D[64,128] = A[64,256] @ Bprep[128rows,256]^T, split-bf16.
// MODE 0: outf = D + bias;  MODE 1: += resid;  MODE 2: gated sigmoid*gelu
// -> bf16 hi/lo (gate = D cols 0-63, value = D cols 64-127).
// smem: 3 stages x {Ah,Al:64rows, Bh,Bl:128rows} x 80 B rows = 92160 B.
// Single __syncthreads per k-iter (ring depth 3, loads issued 2 ahead into
// the stage consumed last iteration).
#define TS3    80
#define A_TILE (64 * TS3)            // 5120
#define B_TILE (128 * TS3)           // 10240
#define STAGE3 (2 * A_TILE + 2 * B_TILE)  // 30720
#define GEMM_SMEM (3 * STAGE3)       // 92160

template<int MODE>
__global__ __launch_bounds__(256, 2)
void gemm_mma_kernel(const __nv_bfloat16* __restrict__ Ahi,
                     const __nv_bfloat16* __restrict__ Alo,
                     const __nv_bfloat16* __restrict__ Bhi,
                     const __nv_bfloat16* __restrict__ Blo,
                     const float* __restrict__ bias, const float* __restrict__ resid,
                     float* __restrict__ outf,
                     __nv_bfloat16* __restrict__ outhi,
                     __nv_bfloat16* __restrict__ outlo) {
    extern __shared__ char sm[];
    unsigned sbase = smem_u32(sm);
    const int tid = threadIdx.x, wid = tid >> 5, lane = tid & 31;
    const int m0 = blockIdx.y * 64;
    const int nb = blockIdx.x;
    const int n0p = nb * 128;

    const char* Ah8 = (const char*)Ahi + (size_t)m0 * 512;
    const char* Al8 = (const char*)Alo + (size_t)m0 * 512;
    const char* Bh8 = (const char*)Bhi + (size_t)n0p * 512;
    const char* Bl8 = (const char*)Blo + (size_t)n0p * 512;

    auto load_stage = [&](int s, int k0) {
        unsigned dst0 = sbase + s * STAGE3;
        int kbyte = k0 * 2;
        {   // A: 64 rows x 4 chunks = 256 = one pass
            int row = tid >> 2, c16 = (tid & 3) * 16;
            unsigned so = (unsigned)(row * TS3 + c16);
            size_t go = (size_t)row * 512 + kbyte + c16;
            CP_ASYNC16(dst0 + so,           Ah8 + go);
            CP_ASYNC16(dst0 + A_TILE + so,  Al8 + go);
        }
        #pragma unroll
        for (int j = 0; j < 2; j++) {   // B: 128 rows x 4 chunks = 512
            int i = tid + j * 256;
            int row = i >> 2, c16 = (i & 3) * 16;
            unsigned so = (unsigned)(row * TS3 + c16);
            size_t go = (size_t)row * 512 + kbyte + c16;
            CP_ASYNC16(dst0 + 2 * A_TILE + so,           Bh8 + go);
            CP_ASYNC16(dst0 + 2 * A_TILE + B_TILE + so,  Bl8 + go);
        }
        CP_COMMIT();
    };

    load_stage(0, 0);
    load_stage(1, 32);

    const int warpM = wid & 1, warpN = wid >> 1;     // 2 x 4 warps, 32x32 tiles
    float acc[2][4][4];
    #pragma unroll
    for (int mt = 0; mt < 2; mt++)
        #pragma unroll
        for (int nt = 0; nt < 4; nt++)
            #pragma unroll
            for (int e = 0; e < 4; e++) acc[mt][nt][e] = 0.0f;

    const unsigned a_row = warpM * 32 + (lane & 15);
    const unsigned a_cofs = ((lane >> 4) << 3) * 2;          // 0 or 16 bytes
    const unsigned b_row = warpN * 32 + (lane & 7);
    const unsigned b_cofs = (((lane >> 3) & 1) << 3) * 2;    // 0 or 16 bytes

    #pragma unroll 1
    for (int i = 0; i < 8; i++) {
        if (i < 7) { CP_WAIT(1); } else { CP_WAIT(0); }
        __syncthreads();
        if (i + 2 < 8) load_stage((i + 2) % 3, (i + 2) * 32);
        unsigned st  = sbase + (i % 3) * STAGE3;
        unsigned ahb = st;
        unsigned alb = st + A_TILE;
        unsigned bhb = st + 2 * A_TILE;
        unsigned blb = st + 2 * A_TILE + B_TILE;
        #pragma unroll
        for (int ks = 0; ks < 2; ks++) {
            unsigned aoff = a_row * TS3 + ks * 32 + a_cofs;
            unsigned ah[2][4], al[2][4];
            ldsm_x4(ah[0], ahb + aoff);
            ldsm_x4(ah[1], ahb + aoff + 16 * TS3);
            ldsm_x4(al[0], alb + aoff);
            ldsm_x4(al[1], alb + aoff + 16 * TS3);
            unsigned boff = b_row * TS3 + ks * 32 + b_cofs;
            #pragma unroll
            for (int nt = 0; nt < 4; nt++) {
                unsigned bh[2], bl[2];
                ldsm_x2(bh, bhb + boff + nt * 8 * TS3);
                ldsm_x2(bl, blb + boff + nt * 8 * TS3);
                #pragma unroll
                for (int mt = 0; mt < 2; mt++) {
                    mma16816(acc[mt][nt], ah[mt], bh);
                    mma16816(acc[mt][nt], ah[mt], bl);
                    mma16816(acc[mt][nt], al[mt], bh);
                }
            }
        }
    }
    __syncthreads();   // all stages consumed; reuse smem for epilogue

    // ---- epilogue: stage D through smem (64 rows x 132-float stride) ----
    float* smf = (float*)sm;
    #pragma unroll
    for (int mt = 0; mt < 2; mt++) {
        #pragma unroll
        for (int nt = 0; nt < 4; nt++) {
            int r = warpM * 32 + mt * 16 + (lane >> 2);
            int c = warpN * 32 + nt * 8 + (lane & 3) * 2;
            smf[r * 132 + c]           = acc[mt][nt][0];
            smf[r * 132 + c + 1]       = acc[mt][nt][1];
            smf[(r + 8) * 132 + c]     = acc[mt][nt][2];
            smf[(r + 8) * 132 + c + 1] = acc[mt][nt][3];
        }
    }
    __syncthreads();

    if (MODE == 2) {
        const int outn0 = nb * 64;
        for (int i = tid; i < 64 * 32; i += 256) {
            int row = i >> 5, c2 = (i & 31) * 2;
            float gg0 = smf[row * 132 + c2]     + bias[outn0 + c2];
            float gg1 = smf[row * 132 + c2 + 1] + bias[outn0 + c2 + 1];
            float vv0 = smf[row * 132 + 64 + c2]     + bias[256 + outn0 + c2];
            float vv1 = smf[row * 132 + 64 + c2 + 1] + bias[256 + outn0 + c2 + 1];
            float s0 = 1.0f / (1.0f + expf(-gg0));
            float s1 = 1.0f / (1.0f + expf(-gg1));
            float e0 = 0.5f * vv0 * (1.0f + erff(vv0 * 0.7071067811865476f));
            float e1 = 0.5f * vv1 * (1.0f + erff(vv1 * 0.7071067811865476f));
            float o0 = s0 * e0, o1 = s1 * e1;
            __nv_bfloat16 h0, l0, h1, l1;
            splitf(o0, h0, l0); splitf(o1, h1, l1);
            __nv_bfloat162 ph; ph.x = h0; ph.y = h1;
            __nv_bfloat162 pl; pl.x = l0; pl.y = l1;
            size_t ob = (size_t)(m0 + row) * DMODEL + outn0 + c2;
            *(__nv_bfloat162*)(outhi + ob) = ph;
            *(__nv_bfloat162*)(outlo + ob) = pl;
        }
    } else {
        for (int i = tid; i < 64 * 32; i += 256) {
            int row = i >> 5, c4 = (i & 31) * 4;
            float4 o;
            o.x = smf[row * 132 + c4]     + bias[n0p + c4];
            o.y = smf[row * 132 + c4 + 1] + bias[n0p + c4 + 1];
            o.z = smf[row * 132 + c4 + 2] + bias[n0p + c4 + 2];
            o.w = smf[row * 132 + c4 + 3] + bias[n0p + c4 + 3];
            size_t base = (size_t)(m0 + row) * DMODEL + n0p + c4;
            if (MODE == 1) {
                float4 rr = *(const float4*)(resid + base);
                o.x += rr.x; o.y += rr.y; o.z += rr.z; o.w += rr.w;
            }
            *(float4*)(outf + base) = o;
        }
    }
}

// ------------------------- mask tail ----------------------------------------
__global__ void fill_ones_kernel(float* __restrict__ p, int n) {
    int i = blockIdx.x * blockDim.x + threadIdx.x;
    if (i < n) p[i] = 1.0f;
}

// ---------------------------------------------------------------------------
extern "C" void kernel_launch(void* const* d_in, const int* in_sizes, int n_in,
                              void* d_out, int out_size) {
    const float* x      = (const float*)d_in[0];
    const void*  mask   = d_in[1];
    const float* in_w   = (const float*)d_in[2];
    const float* in_b   = (const float*)d_in[3];
    const float* ln_g   = (const float*)d_in[4];
    const float* ln_b   = (const float*)d_in[5];
    const float* dw_w   = (const float*)d_in[6];
    const float* dw_b   = (const float*)d_in[7];
    const float* win_w  = (const float*)d_in[8];
    const float* win_b  = (const float*)d_in[9];
    const float* wout_w = (const float*)d_in[10];
    const float* wout_b = (const float*)d_in[11];
    const float* fn_g   = (const float*)d_in[12];
    const float* fn_b   = (const float*)d_in[13];
    float* out = (float*)d_out;

    __nv_bfloat16 *ahi, *alo, *chi, *clo, *whi, *wlo;
    float *h;
    cudaGetSymbolAddress((void**)&ahi, g_ahi);
    cudaGetSymbolAddress((void**)&alo, g_alo);
    cudaGetSymbolAddress((void**)&chi, g_chi);
    cudaGetSymbolAddress((void**)&clo, g_clo);
    cudaGetSymbolAddress((void**)&whi, g_whi);
    cudaGetSymbolAddress((void**)&wlo, g_wlo);
    cudaGetSymbolAddress((void**)&h,   g_h);

    cudaFuncSetAttribute(gemm_mma_kernel<0>,
        cudaFuncAttributeMaxDynamicSharedMemorySize, GEMM_SMEM);
    cudaFuncSetAttribute(gemm_mma_kernel<1>,
        cudaFuncAttributeMaxDynamicSharedMemorySize, GEMM_SMEM);
    cudaFuncSetAttribute(gemm_mma_kernel<2>,
        cudaFuncAttributeMaxDynamicSharedMemorySize, GEMM_SMEM);

    // 1) mask dtype detection + lengths (one launch)
    lengths_kernel<<<BATCH, 256>>>((const unsigned char*)mask);

    // 2) fused weight prep (one launch: 64 + 4*64 + 4*128 = 832 blocks)
    prep_all_w_kernel<<<832, dim3(32, 32)>>>(in_w, wout_w, win_w, whi, wlo);

    // 3) compress to bf16 hi/lo
    compress_kernel<<<dim3(TLEN / 2, BATCH), 128>>>(x);

    // 4) input projection: h = xc @ in_w + in_b   (grid 2 x 128 = 256 CTAs)
    gemm_mma_kernel<0><<<dim3(2, 128), 256, GEMM_SMEM>>>(
        ahi, alo, whi + WOFF_IN, wlo + WOFF_IN, in_b, nullptr, h, nullptr, nullptr);

    // 5) conv blocks
    for (int i = 0; i < NBLK; i++) {
        lnconv_kernel<<<dim3(TLEN / 32, BATCH), 256>>>(
            h, ln_g + i * DMODEL, ln_b + i * DMODEL,
            dw_w + (size_t)i * DMODEL * KSZ, dw_b + i * DMODEL, ahi, alo);
        gemm_mma_kernel<2><<<dim3(4, 128), 256, GEMM_SMEM>>>(
            ahi, alo, whi + WOFF_GATE(i), wlo + WOFF_GATE(i),
            win_b + (size_t)i * 2 * DMODEL, nullptr, nullptr, chi, clo);
        gemm_mma_kernel<1><<<dim3(2, 128), 256, GEMM_SMEM>>>(
            chi, clo, whi + WOFF_WOUT(i), wlo + WOFF_WOUT(i),
            wout_b + i * DMODEL, h, h, nullptr, nullptr);
    }

    // 6) final layer norm -> out
    ln_warp_kernel<<<MROWS / 8, 256>>>(h, fn_g, fn_b, out);

    // 7) comp_mask tail (all True -> 1.0f) if present in out buffer
    int main_elems = MROWS * DMODEL;
    int extra = out_size - main_elems;
    if (extra > 0)
        fill_ones_kernel<<<(extra + 255) / 256, 256>>>(out + main_elems, extra);
}

// round 12
// speedup vs baseline: 1.0026x; 1.0026x over previous
#include <cuda_runtime.h>
#include <cuda_bf16.h>
#include <math.h>

// ---------------------------------------------------------------------------
// RawSequenceEncoder: compress -> in-proj -> 4x conv blocks -> final LN
// B=32, S=4096, D=256, T=256, NB=4, K=5. M = 8192 rows.
// GEMMs: warp-level mma.sync bf16, 2-term bf16 split (hh+hl+lh), fp32 acc.
// R11: break accumulator RAW chains — hoist all ldsm for a k-step, then issue
// mma pass-major (hh over all 8 accs, then hl, then lh). Reuse distance of a
// given accumulator goes 1 -> 8 mma, letting the tensor pipe fill.
// ---------------------------------------------------------------------------

#define BATCH 32
#define SEQ   4096
#define DMODEL 256
#define TLEN  256
#define NBLK  4
#define KSZ   5
#define MROWS (BATCH * TLEN)   // 8192
#define EPSV  1e-5f
#define KDIM  256

// ------------------------- scratch (static, no allocs) ---------------------
static __device__ __nv_bfloat16 g_ahi[MROWS * KDIM];
static __device__ __nv_bfloat16 g_alo[MROWS * KDIM];
static __device__ __nv_bfloat16 g_chi[MROWS * KDIM];
static __device__ __nv_bfloat16 g_clo[MROWS * KDIM];
#define WOFF_IN    0
#define WOFF_WOUT(i) (65536 + (i) * 65536)
#define WOFF_GATE(i) (65536 * 5 + (i) * 131072)
#define WTOT (65536 * 5 + 131072 * 4)
static __device__ __nv_bfloat16 g_whi[WTOT];
static __device__ __nv_bfloat16 g_wlo[WTOT];
static __device__ float g_h[MROWS * DMODEL];
static __device__ int   g_len[BATCH];

// ------------------------- PTX helpers (sm_80-era only) ---------------------
__device__ __forceinline__ unsigned smem_u32(const void* p) {
    unsigned a;
    asm("{ .reg .u64 t; cvta.to.shared.u64 t, %1; cvt.u32.u64 %0, t; }"
        : "=r"(a) : "l"(p));
    return a;
}
#define CP_ASYNC16(dst, src) \
    asm volatile("cp.async.cg.shared.global [%0], [%1], 16;" :: "r"(dst), "l"(src))
#define CP_COMMIT() asm volatile("cp.async.commit_group;" ::: "memory")
#define CP_WAIT(N)  asm volatile("cp.async.wait_group %0;" :: "n"(N) : "memory")

__device__ __forceinline__ void ldsm_x4(unsigned* r, unsigned addr) {
    asm volatile("ldmatrix.sync.aligned.m8n8.x4.shared.b16 {%0,%1,%2,%3}, [%4];"
                 : "=r"(r[0]), "=r"(r[1]), "=r"(r[2]), "=r"(r[3]) : "r"(addr));
}
__device__ __forceinline__ void ldsm_x2(unsigned* r, unsigned addr) {
    asm volatile("ldmatrix.sync.aligned.m8n8.x2.shared.b16 {%0,%1}, [%2];"
                 : "=r"(r[0]), "=r"(r[1]) : "r"(addr));
}
__device__ __forceinline__ void mma16816(float* d, const unsigned* a, const unsigned* b) {
    asm volatile("mma.sync.aligned.m16n8k16.row.col.f32.bf16.bf16.f32 "
                 "{%0,%1,%2,%3}, {%4,%5,%6,%7}, {%8,%9}, {%0,%1,%2,%3};"
                 : "+f"(d[0]), "+f"(d[1]), "+f"(d[2]), "+f"(d[3])
                 : "r"(a[0]), "r"(a[1]), "r"(a[2]), "r"(a[3]),
                   "r"(b[0]), "r"(b[1]));
}

__device__ __forceinline__ void splitf(float x, __nv_bfloat16& h, __nv_bfloat16& l) {
    h = __float2bfloat16_rn(x);
    l = __float2bfloat16_rn(x - __bfloat162float(h));
}

// ------------------------- fused mask detect + lengths ----------------------
__global__ __launch_bounds__(256)
void lengths_kernel(const unsigned char* __restrict__ maskp) {
    __shared__ float sh[8];
    __shared__ int sflags;   // bit0 = saw byte>1 (f32), bit1 = nonzero at i%4!=0 (u8)
    int b = blockIdx.x;
    if (threadIdx.x == 0) sflags = 0;
    __syncthreads();

    const unsigned* pw = (const unsigned*)maskp;
    const int nwords = (BATCH * SEQ) / 4;   // safe lower bound across dtypes
    int fl = 0;
    for (int i = threadIdx.x; i < nwords; i += 256) {
        unsigned w = pw[i];
        unsigned b0 = w & 0xFF, b1 = (w >> 8) & 0xFF,
                 b2 = (w >> 16) & 0xFF, b3 = w >> 24;
        if (b0 > 1 || b1 > 1 || b2 > 1 || b3 > 1) fl |= 1;
        if (w & 0xFFFFFF00u) fl |= 2;
    }
    if (__any_sync(0xffffffffu, fl & 1)) fl |= 1;
    if (__any_sync(0xffffffffu, fl & 2)) fl |= 2;
    if ((threadIdx.x & 31) == 0 && fl) atomicOr(&sflags, fl);
    __syncthreads();
    int kind = (sflags & 1) ? 2 : ((sflags & 2) ? 0 : 1); // 2=f32, 0=u8, 1=i32

    float local = 0.0f;
    if (kind == 0) {
        const unsigned char* p = maskp + (size_t)b * SEQ;
        for (int i = threadIdx.x; i < SEQ; i += 256) local += (float)p[i];
    } else if (kind == 1) {
        const int* p = (const int*)maskp + (size_t)b * SEQ;
        for (int i = threadIdx.x; i < SEQ; i += 256) local += (float)p[i];
    } else {
        const float* p = (const float*)maskp + (size_t)b * SEQ;
        for (int i = threadIdx.x; i < SEQ; i += 256) local += p[i];
    }
    int lane = threadIdx.x & 31, w = threadIdx.x >> 5;
    #pragma unroll
    for (int o = 16; o > 0; o >>= 1) local += __shfl_down_sync(0xffffffffu, local, o);
    if (lane == 0) sh[w] = local;
    __syncthreads();
    if (threadIdx.x == 0) {
        float tot = 0.0f;
        #pragma unroll
        for (int i = 0; i < 8; i++) tot += sh[i];
        g_len[b] = (int)lrintf(tot);
    }
}

// ------------------------- compress -> bf16 hi/lo ----------------------------
__global__ void compress_kernel(const float* __restrict__ x) {
    int b = blockIdx.y;
    int t = blockIdx.x * 2 + (threadIdx.x >> 6);
    int lane = threadIdx.x & 63;
    int L = g_len[b];
    float Lf  = (float)L;
    float src = ((float)t + 0.5f) * (Lf * (1.0f / (float)TLEN)) - 0.5f;
    float hi  = fmaxf(Lf - 1.0f, 0.0f);
    src = fminf(fmaxf(src, 0.0f), hi);
    int   i0 = (int)floorf(src);
    int   i1 = min(i0 + 1, max(L - 1, 0));
    float w  = src - (float)i0;
    const float4* r0 = (const float4*)(x + ((size_t)b * SEQ + i0) * DMODEL);
    const float4* r1 = (const float4*)(x + ((size_t)b * SEQ + i1) * DMODEL);
    float4 v0 = r0[lane], v1 = r1[lane];
    float o[4];
    o[0] = (1.0f - w) * v0.x + w * v1.x;
    o[1] = (1.0f - w) * v0.y + w * v1.y;
    o[2] = (1.0f - w) * v0.z + w * v1.z;
    o[3] = (1.0f - w) * v0.w + w * v1.w;
    size_t base = ((size_t)(b * TLEN + t)) * DMODEL + lane * 4;
    __nv_bfloat16 h0, l0, h1, l1;
    splitf(o[0], h0, l0); splitf(o[1], h1, l1);
    __nv_bfloat162 ph0; ph0.x = h0; ph0.y = h1;
    __nv_bfloat162 pl0; pl0.x = l0; pl0.y = l1;
    splitf(o[2], h0, l0); splitf(o[3], h1, l1);
    __nv_bfloat162 ph1; ph1.x = h0; ph1.y = h1;
    __nv_bfloat162 pl1; pl1.x = l0; pl1.y = l1;
    *(__nv_bfloat162*)(g_ahi + base)     = ph0;
    *(__nv_bfloat162*)(g_ahi + base + 2) = ph1;
    *(__nv_bfloat162*)(g_alo + base)     = pl0;
    *(__nv_bfloat162*)(g_alo + base + 2) = pl1;
}

// ------------------------- fused weight prep (ONE launch) -------------------
__global__ void prep_all_w_kernel(const float* __restrict__ in_w,
                                  const float* __restrict__ wout_w,
                                  const float* __restrict__ win_w,
                                  __nv_bfloat16* __restrict__ hi,
                                  __nv_bfloat16* __restrict__ lo) {
    __shared__ float t[32][33];
    int bid = blockIdx.x;
    const float* W;
    int srcld, gated, tile;
    size_t dsto;
    if (bid < 64) {
        W = in_w; srcld = 256; gated = 0; dsto = WOFF_IN; tile = bid;
    } else if (bid < 320) {
        int tt = bid - 64, i = tt >> 6;
        W = wout_w + (size_t)i * 65536; srcld = 256; gated = 0;
        dsto = WOFF_WOUT(i); tile = tt & 63;
    } else {
        int tt = bid - 320, i = tt >> 7;
        W = win_w + (size_t)i * 131072; srcld = 512; gated = 1;
        dsto = WOFF_GATE(i); tile = tt & 127;
    }
    int kx = (tile & 7) * 32, py = (tile >> 3) * 32;
    int tx = threadIdx.x, ty = threadIdx.y;
    int p = py + tx;
    int srccol;
    if (gated) {
        int j = p >> 7, r5 = p & 127;
        srccol = j * 64 + (r5 & 63) + ((r5 & 64) ? 256 : 0);
    } else srccol = p;
    t[ty][tx] = W[(size_t)(kx + ty) * srcld + srccol];
    __syncthreads();
    int pp = py + ty, k = kx + tx;
    __nv_bfloat16 h, l;
    splitf(t[tx][ty], h, l);
    hi[dsto + (size_t)pp * KDIM + k] = h;
    lo[dsto + (size_t)pp * KDIM + k] = l;
}

// ------------------------- fused LN + conv -> bf16 hi/lo --------------------
__global__ __launch_bounds__(256)
void lnconv_kernel(const float* __restrict__ h,
                   const float* __restrict__ g, const float* __restrict__ bta,
                   const float* __restrict__ w, const float* __restrict__ cbias,
                   __nv_bfloat16* __restrict__ ohi, __nv_bfloat16* __restrict__ olo) {
    __shared__ float sh[36][DMODEL];
    int b = blockIdx.y;
    int t0 = blockIdx.x * 32;
    int warp = threadIdx.x >> 5, lane = threadIdx.x & 31;

    for (int r = warp; r < 36; r += 8) {
        int t = t0 - 2 + r;
        if (t < 0 || t >= TLEN) {
            float4 z = make_float4(0.f, 0.f, 0.f, 0.f);
            ((float4*)sh[r])[lane * 2]     = z;
            ((float4*)sh[r])[lane * 2 + 1] = z;
        } else {
            const float4* p = (const float4*)(h + ((size_t)(b * TLEN + t)) * DMODEL);
            float4 v0 = p[lane * 2], v1 = p[lane * 2 + 1];
            float s  = v0.x + v0.y + v0.z + v0.w + v1.x + v1.y + v1.z + v1.w;
            float sq = v0.x*v0.x + v0.y*v0.y + v0.z*v0.z + v0.w*v0.w
                     + v1.x*v1.x + v1.y*v1.y + v1.z*v1.z + v1.w*v1.w;
            #pragma unroll
            for (int o = 16; o > 0; o >>= 1) {
                s  += __shfl_xor_sync(0xffffffffu, s,  o);
                sq += __shfl_xor_sync(0xffffffffu, sq, o);
            }
            float mu  = s  * (1.0f / (float)DMODEL);
            float var = sq * (1.0f / (float)DMODEL) - mu * mu;
            float rs  = rsqrtf(var + EPSV);
            const float4* gp = (const float4*)g;
            const float4* bp = (const float4*)bta;
            float4 g0 = gp[lane * 2], g1 = gp[lane * 2 + 1];
            float4 b0 = bp[lane * 2], b1 = bp[lane * 2 + 1];
            float4 o0, o1;
            o0.x = (v0.x - mu) * rs * g0.x + b0.x;
            o0.y = (v0.y - mu) * rs * g0.y + b0.y;
            o0.z = (v0.z - mu) * rs * g0.z + b0.z;
            o0.w = (v0.w - mu) * rs * g0.w + b0.w;
            o1.x = (v1.x - mu) * rs * g1.x + b1.x;
            o1.y = (v1.y - mu) * rs * g1.y + b1.y;
            o1.z = (v1.z - mu) * rs * g1.z + b1.z;
            o1.w = (v1.w - mu) * rs * g1.w + b1.w;
            ((float4*)sh[r])[lane * 2]     = o0;
            ((float4*)sh[r])[lane * 2 + 1] = o1;
        }
    }
    __syncthreads();

    int d = threadIdx.x;
    float w0 = w[d * KSZ + 0], w1 = w[d * KSZ + 1], w2 = w[d * KSZ + 2];
    float w3 = w[d * KSZ + 3], w4 = w[d * KSZ + 4];
    float cb = cbias[d];
    float acc[32];
    #pragma unroll
    for (int t = 0; t < 32; t++) {
        float a = cb;
        a = fmaf(w0, sh[t    ][d], a);
        a = fmaf(w1, sh[t + 1][d], a);
        a = fmaf(w2, sh[t + 2][d], a);
        a = fmaf(w3, sh[t + 3][d], a);
        a = fmaf(w4, sh[t + 4][d], a);
        acc[t] = a;
    }
    __syncthreads();
    #pragma unroll
    for (int t = 0; t < 32; t++) sh[t][d] = acc[t];
    __syncthreads();

    size_t rowbase = (size_t)(b * TLEN + t0);
    for (int p = threadIdx.x; p < 32 * 128; p += 256) {
        int r = p >> 7, dp = (p & 127) * 2;
        __nv_bfloat16 h0, l0, h1, l1;
        splitf(sh[r][dp],     h0, l0);
        splitf(sh[r][dp + 1], h1, l1);
        __nv_bfloat162 ph; ph.x = h0; ph.y = h1;
        __nv_bfloat162 pl; pl.x = l0; pl.y = l1;
        *(__nv_bfloat162*)(ohi + (rowbase + r) * DMODEL + dp) = ph;
        *(__nv_bfloat162*)(olo + (rowbase + r) * DMODEL + dp) = pl;
    }
}

// ------------------------- warp-per-row final layer norm --------------------
__global__ void ln_warp_kernel(const float* __restrict__ in,
                               const float* __restrict__ g,
                               const float* __restrict__ bta,
                               float* __restrict__ out) {
    int warp = threadIdx.x >> 5, lane = threadIdx.x & 31;
    int m = blockIdx.x * 8 + warp;
    const float4* p = (const float4*)(in + (size_t)m * DMODEL);
    float4 v0 = p[lane * 2], v1 = p[lane * 2 + 1];
    float s  = v0.x + v0.y + v0.z + v0.w + v1.x + v1.y + v1.z + v1.w;
    float sq = v0.x*v0.x + v0.y*v0.y + v0.z*v0.z + v0.w*v0.w
             + v1.x*v1.x + v1.y*v1.y + v1.z*v1.z + v1.w*v1.w;
    #pragma unroll
    for (int o = 16; o > 0; o >>= 1) {
        s  += __shfl_xor_sync(0xffffffffu, s,  o);
        sq += __shfl_xor_sync(0xffffffffu, sq, o);
    }
    float mu  = s  * (1.0f / (float)DMODEL);
    float var = sq * (1.0f / (float)DMODEL) - mu * mu;
    float rs  = rsqrtf(var + EPSV);
    const float4* gp = (const float4*)g;
    const float4* bp = (const float4*)bta;
    float4 g0 = gp[lane * 2], g1 = gp[lane * 2 + 1];
    float4 b0 = bp[lane * 2], b1 = bp[lane * 2 + 1];
    float4 o0, o1;
    o0.x = (v0.x - mu) * rs * g0.x + b0.x;
    o0.y = (v0.y - mu) * rs * g0.y + b0.y;
    o0.z = (v0.z - mu) * rs * g0.z + b0.z;
    o0.w = (v0.w - mu) * rs * g0.w + b0.w;
    o1.x = (v1.x - mu) * rs * g1.x + b1.x;
    o1.y = (v1.y - mu) * rs * g1.y + b1.y;
    o1.z = (v1.z - mu) * rs * g1.z + b1.z;
    o1.w = (v1.w - mu) * rs * g1.w + b1.w;
    ((float4*)(out + (size_t)m * DMODEL))[lane * 2]     = o0;
    ((float4*)(out + (size_t)m * DMODEL))[lane * 2 + 1] = o1;
}

// ------------------------- mma.sync GEMM (64x128 tile, 3-stage ring) --------
// Per CTA: D[64,128] = A[64,256] @ Bprep[128rows,256]^T, split-bf16.
// MODE 0: outf = D + bias;  MODE 1: += resid;  MODE 2: gated sigmoid*gelu
// -> bf16 hi/lo (gate = D cols 0-63, value = D cols 64-127).
// smem: 3 stages x {Ah,Al:64rows, Bh,Bl:128rows} x 80 B rows = 92160 B.
// Mainloop: all 12 ldsm hoisted per k-step, then 48 mma issued pass-major
// (hh, hl, lh) so same-accumulator reuse distance is 8 mma (pipe fills).
#define TS3    80
#define A_TILE (64 * TS3)            // 5120
#define B_TILE (128 * TS3)           // 10240
#define STAGE3 (2 * A_TILE + 2 * B_TILE)  // 30720
#define GEMM_SMEM (3 * STAGE3)       // 92160

template<int MODE>
__global__ __launch_bounds__(256, 2)
void gemm_mma_kernel(const __nv_bfloat16* __restrict__ Ahi,
                     const __nv_bfloat16* __restrict__ Alo,
                     const __nv_bfloat16* __restrict__ Bhi,
                     const __nv_bfloat16* __restrict__ Blo,
                     const float* __restrict__ bias, const float* __restrict__ resid,
                     float* __restrict__ outf,
                     __nv_bfloat16* __restrict__ outhi,
                     __nv_bfloat16* __restrict__ outlo) {
    extern __shared__ char sm[];
    unsigned sbase = smem_u32(sm);
    const int tid = threadIdx.x, wid = tid >> 5, lane = tid & 31;
    const int m0 = blockIdx.y * 64;
    const int nb = blockIdx.x;
    const int n0p = nb * 128;

    const char* Ah8 = (const char*)Ahi + (size_t)m0 * 512;
    const char* Al8 = (const char*)Alo + (size_t)m0 * 512;
    const char* Bh8 = (const char*)Bhi + (size_t)n0p * 512;
    const char* Bl8 = (const char*)Blo + (size_t)n0p * 512;

    auto load_stage = [&](int s, int k0) {
        unsigned dst0 = sbase + s * STAGE3;
        int kbyte = k0 * 2;
        {   // A: 64 rows x 4 chunks = 256 = one pass
            int row = tid >> 2, c16 = (tid & 3) * 16;
            unsigned so = (unsigned)(row * TS3 + c16);
            size_t go = (size_t)row * 512 + kbyte + c16;
            CP_ASYNC16(dst0 + so,           Ah8 + go);
            CP_ASYNC16(dst0 + A_TILE + so,  Al8 + go);
        }
        #pragma unroll
        for (int j = 0; j < 2; j++) {   // B: 128 rows x 4 chunks = 512
            int i = tid + j * 256;
            int row = i >> 2, c16 = (i & 3) * 16;
            unsigned so = (unsigned)(row * TS3 + c16);
            size_t go = (size_t)row * 512 + kbyte + c16;
            CP_ASYNC16(dst0 + 2 * A_TILE + so,           Bh8 + go);
            CP_ASYNC16(dst0 + 2 * A_TILE + B_TILE + so,  Bl8 + go);
        }
        CP_COMMIT();
    };

    load_stage(0, 0);
    load_stage(1, 32);

    const int warpM = wid & 1, warpN = wid >> 1;     // 2 x 4 warps, 32x32 tiles
    float acc[2][4][4];
    #pragma unroll
    for (int mt = 0; mt < 2; mt++)
        #pragma unroll
        for (int nt = 0; nt < 4; nt++)
            #pragma unroll
            for (int e = 0; e < 4; e++) acc[mt][nt][e] = 0.0f;

    const unsigned a_row = warpM * 32 + (lane & 15);
    const unsigned a_cofs = ((lane >> 4) << 3) * 2;          // 0 or 16 bytes
    const unsigned b_row = warpN * 32 + (lane & 7);
    const unsigned b_cofs = (((lane >> 3) & 1) << 3) * 2;    // 0 or 16 bytes

    #pragma unroll 1
    for (int i = 0; i < 8; i++) {
        if (i < 7) { CP_WAIT(1); } else { CP_WAIT(0); }
        __syncthreads();
        if (i + 2 < 8) load_stage((i + 2) % 3, (i + 2) * 32);
        unsigned st  = sbase + (i % 3) * STAGE3;
        unsigned ahb = st;
        unsigned alb = st + A_TILE;
        unsigned bhb = st + 2 * A_TILE;
        unsigned blb = st + 2 * A_TILE + B_TILE;
        #pragma unroll
        for (int ks = 0; ks < 2; ks++) {
            // ---- hoist ALL fragment loads for this k16 step ----
            unsigned aoff = a_row * TS3 + ks * 32 + a_cofs;
            unsigned boff = b_row * TS3 + ks * 32 + b_cofs;
            unsigned ah[2][4], al[2][4];
            unsigned bh[4][2], bl[4][2];
            ldsm_x4(ah[0], ahb + aoff);
            ldsm_x4(ah[1], ahb + aoff + 16 * TS3);
            ldsm_x4(al[0], alb + aoff);
            ldsm_x4(al[1], alb + aoff + 16 * TS3);
            #pragma unroll
            for (int nt = 0; nt < 4; nt++) {
                ldsm_x2(bh[nt], bhb + boff + nt * 8 * TS3);
                ldsm_x2(bl[nt], blb + boff + nt * 8 * TS3);
            }
            // ---- pass 1: hi x hi (8 independent accumulators) ----
            #pragma unroll
            for (int nt = 0; nt < 4; nt++)
                #pragma unroll
                for (int mt = 0; mt < 2; mt++)
                    mma16816(acc[mt][nt], ah[mt], bh[nt]);
            // ---- pass 2: hi x lo ----
            #pragma unroll
            for (int nt = 0; nt < 4; nt++)
                #pragma unroll
                for (int mt = 0; mt < 2; mt++)
                    mma16816(acc[mt][nt], ah[mt], bl[nt]);
            // ---- pass 3: lo x hi ----
            #pragma unroll
            for (int nt = 0; nt < 4; nt++)
                #pragma unroll
                for (int mt = 0; mt < 2; mt++)
                    mma16816(acc[mt][nt], al[mt], bh[nt]);
        }
    }
    __syncthreads();   // all stages consumed; reuse smem for epilogue

    // ---- epilogue: stage D through smem (64 rows x 132-float stride) ----
    float* smf = (float*)sm;
    #pragma unroll
    for (int mt = 0; mt < 2; mt++) {
        #pragma unroll
        for (int nt = 0; nt < 4; nt++) {
            int r = warpM * 32 + mt * 16 + (lane >> 2);
            int c = warpN * 32 + nt * 8 + (lane & 3) * 2;
            smf[r * 132 + c]           = acc[mt][nt][0];
            smf[r * 132 + c + 1]       = acc[mt][nt][1];
            smf[(r + 8) * 132 + c]     = acc[mt][nt][2];
            smf[(r + 8) * 132 + c + 1] = acc[mt][nt][3];
        }
    }
    __syncthreads();

    if (MODE == 2) {
        const int outn0 = nb * 64;
        for (int i = tid; i < 64 * 32; i += 256) {
            int row = i >> 5, c2 = (i & 31) * 2;
            float gg0 = smf[row * 132 + c2]     + bias[outn0 + c2];
            float gg1 = smf[row * 132 + c2 + 1] + bias[outn0 + c2 + 1];
            float vv0 = smf[row * 132 + 64 + c2]     + bias[256 + outn0 + c2];
            float vv1 = smf[row * 132 + 64 + c2 + 1] + bias[256 + outn0 + c2 + 1];
            float s0 = 1.0f / (1.0f + expf(-gg0));
            float s1 = 1.0f / (1.0f + expf(-gg1));
            float e0 = 0.5f * vv0 * (1.0f + erff(vv0 * 0.7071067811865476f));
            float e1 = 0.5f * vv1 * (1.0f + erff(vv1 * 0.7071067811865476f));
            float o0 = s0 * e0, o1 = s1 * e1;
            __nv_bfloat16 h0, l0, h1, l1;
            splitf(o0, h0, l0); splitf(o1, h1, l1);
            __nv_bfloat162 ph; ph.x = h0; ph.y = h1;
            __nv_bfloat162 pl; pl.x = l0; pl.y = l1;
            size_t ob = (size_t)(m0 + row) * DMODEL + outn0 + c2;
            *(__nv_bfloat162*)(outhi + ob) = ph;
            *(__nv_bfloat162*)(outlo + ob) = pl;
        }
    } else {
        for (int i = tid; i < 64 * 32; i += 256) {
            int row = i >> 5, c4 = (i & 31) * 4;
            float4 o;
            o.x = smf[row * 132 + c4]     + bias[n0p + c4];
            o.y = smf[row * 132 + c4 + 1] + bias[n0p + c4 + 1];
            o.z = smf[row * 132 + c4 + 2] + bias[n0p + c4 + 2];
            o.w = smf[row * 132 + c4 + 3] + bias[n0p + c4 + 3];
            size_t base = (size_t)(m0 + row) * DMODEL + n0p + c4;
            if (MODE == 1) {
                float4 rr = *(const float4*)(resid + base);
                o.x += rr.x; o.y += rr.y; o.z += rr.z; o.w += rr.w;
            }
            *(float4*)(outf + base) = o;
        }
    }
}

// ------------------------- mask tail ----------------------------------------
__global__ void fill_ones_kernel(float* __restrict__ p, int n) {
    int i = blockIdx.x * blockDim.x + threadIdx.x;
    if (i < n) p[i] = 1.0f;
}

// ---------------------------------------------------------------------------
extern "C" void kernel_launch(void* const* d_in, const int* in_sizes, int n_in,
                              void* d_out, int out_size) {
    const float* x      = (const float*)d_in[0];
    const void*  mask   = d_in[1];
    const float* in_w   = (const float*)d_in[2];
    const float* in_b   = (const float*)d_in[3];
    const float* ln_g   = (const float*)d_in[4];
    const float* ln_b   = (const float*)d_in[5];
    const float* dw_w   = (const float*)d_in[6];
    const float* dw_b   = (const float*)d_in[7];
    const float* win_w  = (const float*)d_in[8];
    const float* win_b  = (const float*)d_in[9];
    const float* wout_w = (const float*)d_in[10];
    const float* wout_b = (const float*)d_in[11];
    const float* fn_g   = (const float*)d_in[12];
    const float* fn_b   = (const float*)d_in[13];
    float* out = (float*)d_out;

    __nv_bfloat16 *ahi, *alo, *chi, *clo, *whi, *wlo;
    float *h;
    cudaGetSymbolAddress((void**)&ahi, g_ahi);
    cudaGetSymbolAddress((void**)&alo, g_alo);
    cudaGetSymbolAddress((void**)&chi, g_chi);
    cudaGetSymbolAddress((void**)&clo, g_clo);
    cudaGetSymbolAddress((void**)&whi, g_whi);
    cudaGetSymbolAddress((void**)&wlo, g_wlo);
    cudaGetSymbolAddress((void**)&h,   g_h);

    cudaFuncSetAttribute(gemm_mma_kernel<0>,
        cudaFuncAttributeMaxDynamicSharedMemorySize, GEMM_SMEM);
    cudaFuncSetAttribute(gemm_mma_kernel<1>,
        cudaFuncAttributeMaxDynamicSharedMemorySize, GEMM_SMEM);
    cudaFuncSetAttribute(gemm_mma_kernel<2>,
        cudaFuncAttributeMaxDynamicSharedMemorySize, GEMM_SMEM);

    // 1) mask dtype detection + lengths (one launch)
    lengths_kernel<<<BATCH, 256>>>((const unsigned char*)mask);

    // 2) fused weight prep (one launch: 64 + 4*64 + 4*128 = 832 blocks)
    prep_all_w_kernel<<<832, dim3(32, 32)>>>(in_w, wout_w, win_w, whi, wlo);

    // 3) compress to bf16 hi/lo
    compress_kernel<<<dim3(TLEN / 2, BATCH), 128>>>(x);

    // 4) input projection: h = xc @ in_w + in_b   (grid 2 x 128 = 256 CTAs)
    gemm_mma_kernel<0><<<dim3(2, 128), 256, GEMM_SMEM>>>(
        ahi, alo, whi + WOFF_IN, wlo + WOFF_IN, in_b, nullptr, h, nullptr, nullptr);

    // 5) conv blocks
    for (int i = 0; i < NBLK; i++) {
        lnconv_kernel<<<dim3(TLEN / 32, BATCH), 256>>>(
            h, ln_g + i * DMODEL, ln_b + i * DMODEL,
            dw_w + (size_t)i * DMODEL * KSZ, dw_b + i * DMODEL, ahi, alo);
        gemm_mma_kernel<2><<<dim3(4, 128), 256, GEMM_SMEM>>>(
            ahi, alo, whi + WOFF_GATE(i), wlo + WOFF_GATE(i),
            win_b + (size_t)i * 2 * DMODEL, nullptr, nullptr, chi, clo);
        gemm_mma_kernel<1><<<dim3(2, 128), 256, GEMM_SMEM>>>(
            chi, clo, whi + WOFF_WOUT(i), wlo + WOFF_WOUT(i),
            wout_b + i * DMODEL, h, h, nullptr, nullptr);
    }

    // 6) final layer norm -> out
    ln_warp_kernel<<<MROWS / 8, 256>>>(h, fn_g, fn_b, out);

    // 7) comp_mask tail (all True -> 1.0f) if present in out buffer
    int main_elems = MROWS * DMODEL;
    int extra = out_size - main_elems;
    if (extra > 0)
        fill_ones_kernel<<<(extra + 255) / 256, 256>>>(out + main_elems, extra);
}

// round 13
// speedup vs baseline: 1.5895x; 1.5854x over previous
#include <cuda_runtime.h>
#include <cuda_bf16.h>
#include <cuda_fp16.h>
#include <math.h>

// ---------------------------------------------------------------------------
// RawSequenceEncoder: compress -> in-proj -> 4x conv blocks -> final LN
// B=32, S=4096, D=256, T=256, NB=4, K=5. M = 8192 rows.
// R13: single-pass fp16 mma.sync GEMMs (fp32 accumulate). Replaces the
// 3-pass split-bf16 engine: 3x fewer mma, 2x less smem/global traffic.
// Predicted rel_err ~1-3e-4 (vs 4.4e-6 for split-bf16), threshold 1e-3.
// ---------------------------------------------------------------------------

#define BATCH 32
#define SEQ   4096
#define DMODEL 256
#define TLEN  256
#define NBLK  4
#define KSZ   5
#define MROWS (BATCH * TLEN)   // 8192
#define EPSV  1e-5f
#define KDIM  256

// ------------------------- scratch (static, no allocs) ---------------------
static __device__ __half g_a[MROWS * KDIM];   // activations (compress / lnconv out)
static __device__ __half g_c[MROWS * KDIM];   // gated activation out
#define WOFF_IN    0
#define WOFF_WOUT(i) (65536 + (i) * 65536)
#define WOFF_GATE(i) (65536 * 5 + (i) * 131072)
#define WTOT (65536 * 5 + 131072 * 4)
static __device__ __half g_w[WTOT];           // prepped weights [N,K] fp16
static __device__ float g_h[MROWS * DMODEL];
static __device__ int   g_len[BATCH];

// ------------------------- PTX helpers (sm_80-era only) ---------------------
__device__ __forceinline__ unsigned smem_u32(const void* p) {
    unsigned a;
    asm("{ .reg .u64 t; cvta.to.shared.u64 t, %1; cvt.u32.u64 %0, t; }"
        : "=r"(a) : "l"(p));
    return a;
}
#define CP_ASYNC16(dst, src) \
    asm volatile("cp.async.cg.shared.global [%0], [%1], 16;" :: "r"(dst), "l"(src))
#define CP_COMMIT() asm volatile("cp.async.commit_group;" ::: "memory")
#define CP_WAIT(N)  asm volatile("cp.async.wait_group %0;" :: "n"(N) : "memory")

__device__ __forceinline__ void ldsm_x4(unsigned* r, unsigned addr) {
    asm volatile("ldmatrix.sync.aligned.m8n8.x4.shared.b16 {%0,%1,%2,%3}, [%4];"
                 : "=r"(r[0]), "=r"(r[1]), "=r"(r[2]), "=r"(r[3]) : "r"(addr));
}
__device__ __forceinline__ void ldsm_x2(unsigned* r, unsigned addr) {
    asm volatile("ldmatrix.sync.aligned.m8n8.x2.shared.b16 {%0,%1}, [%2];"
                 : "=r"(r[0]), "=r"(r[1]) : "r"(addr));
}
__device__ __forceinline__ void mma16816h(float* d, const unsigned* a, const unsigned* b) {
    asm volatile("mma.sync.aligned.m16n8k16.row.col.f32.f16.f16.f32 "
                 "{%0,%1,%2,%3}, {%4,%5,%6,%7}, {%8,%9}, {%0,%1,%2,%3};"
                 : "+f"(d[0]), "+f"(d[1]), "+f"(d[2]), "+f"(d[3])
                 : "r"(a[0]), "r"(a[1]), "r"(a[2]), "r"(a[3]),
                   "r"(b[0]), "r"(b[1]));
}

// ------------------------- fused mask detect + lengths ----------------------
__global__ __launch_bounds__(256)
void lengths_kernel(const unsigned char* __restrict__ maskp) {
    __shared__ float sh[8];
    __shared__ int sflags;   // bit0 = saw byte>1 (f32), bit1 = nonzero at i%4!=0 (u8)
    int b = blockIdx.x;
    if (threadIdx.x == 0) sflags = 0;
    __syncthreads();

    const unsigned* pw = (const unsigned*)maskp;
    const int nwords = (BATCH * SEQ) / 4;   // safe lower bound across dtypes
    int fl = 0;
    for (int i = threadIdx.x; i < nwords; i += 256) {
        unsigned w = pw[i];
        unsigned b0 = w & 0xFF, b1 = (w >> 8) & 0xFF,
                 b2 = (w >> 16) & 0xFF, b3 = w >> 24;
        if (b0 > 1 || b1 > 1 || b2 > 1 || b3 > 1) fl |= 1;
        if (w & 0xFFFFFF00u) fl |= 2;
    }
    if (__any_sync(0xffffffffu, fl & 1)) fl |= 1;
    if (__any_sync(0xffffffffu, fl & 2)) fl |= 2;
    if ((threadIdx.x & 31) == 0 && fl) atomicOr(&sflags, fl);
    __syncthreads();
    int kind = (sflags & 1) ? 2 : ((sflags & 2) ? 0 : 1); // 2=f32, 0=u8, 1=i32

    float local = 0.0f;
    if (kind == 0) {
        const unsigned char* p = maskp + (size_t)b * SEQ;
        for (int i = threadIdx.x; i < SEQ; i += 256) local += (float)p[i];
    } else if (kind == 1) {
        const int* p = (const int*)maskp + (size_t)b * SEQ;
        for (int i = threadIdx.x; i < SEQ; i += 256) local += (float)p[i];
    } else {
        const float* p = (const float*)maskp + (size_t)b * SEQ;
        for (int i = threadIdx.x; i < SEQ; i += 256) local += p[i];
    }
    int lane = threadIdx.x & 31, w = threadIdx.x >> 5;
    #pragma unroll
    for (int o = 16; o > 0; o >>= 1) local += __shfl_down_sync(0xffffffffu, local, o);
    if (lane == 0) sh[w] = local;
    __syncthreads();
    if (threadIdx.x == 0) {
        float tot = 0.0f;
        #pragma unroll
        for (int i = 0; i < 8; i++) tot += sh[i];
        g_len[b] = (int)lrintf(tot);
    }
}

// ------------------------- compress -> fp16 ----------------------------------
__global__ void compress_kernel(const float* __restrict__ x) {
    int b = blockIdx.y;
    int t = blockIdx.x * 2 + (threadIdx.x >> 6);
    int lane = threadIdx.x & 63;
    int L = g_len[b];
    float Lf  = (float)L;
    float src = ((float)t + 0.5f) * (Lf * (1.0f / (float)TLEN)) - 0.5f;
    float hi  = fmaxf(Lf - 1.0f, 0.0f);
    src = fminf(fmaxf(src, 0.0f), hi);
    int   i0 = (int)floorf(src);
    int   i1 = min(i0 + 1, max(L - 1, 0));
    float w  = src - (float)i0;
    const float4* r0 = (const float4*)(x + ((size_t)b * SEQ + i0) * DMODEL);
    const float4* r1 = (const float4*)(x + ((size_t)b * SEQ + i1) * DMODEL);
    float4 v0 = r0[lane], v1 = r1[lane];
    float o[4];
    o[0] = (1.0f - w) * v0.x + w * v1.x;
    o[1] = (1.0f - w) * v0.y + w * v1.y;
    o[2] = (1.0f - w) * v0.z + w * v1.z;
    o[3] = (1.0f - w) * v0.w + w * v1.w;
    size_t base = ((size_t)(b * TLEN + t)) * DMODEL + lane * 4;
    __half2 p0, p1;
    p0.x = __float2half_rn(o[0]); p0.y = __float2half_rn(o[1]);
    p1.x = __float2half_rn(o[2]); p1.y = __float2half_rn(o[3]);
    *(__half2*)(g_a + base)     = p0;
    *(__half2*)(g_a + base + 2) = p1;
}

// ------------------------- fused weight prep (ONE launch) -------------------
__global__ void prep_all_w_kernel(const float* __restrict__ in_w,
                                  const float* __restrict__ wout_w,
                                  const float* __restrict__ win_w,
                                  __half* __restrict__ wdst) {
    __shared__ float t[32][33];
    int bid = blockIdx.x;
    const float* W;
    int srcld, gated, tile;
    size_t dsto;
    if (bid < 64) {
        W = in_w; srcld = 256; gated = 0; dsto = WOFF_IN; tile = bid;
    } else if (bid < 320) {
        int tt = bid - 64, i = tt >> 6;
        W = wout_w + (size_t)i * 65536; srcld = 256; gated = 0;
        dsto = WOFF_WOUT(i); tile = tt & 63;
    } else {
        int tt = bid - 320, i = tt >> 7;
        W = win_w + (size_t)i * 131072; srcld = 512; gated = 1;
        dsto = WOFF_GATE(i); tile = tt & 127;
    }
    int kx = (tile & 7) * 32, py = (tile >> 3) * 32;
    int tx = threadIdx.x, ty = threadIdx.y;
    int p = py + tx;
    int srccol;
    if (gated) {
        int j = p >> 7, r5 = p & 127;
        srccol = j * 64 + (r5 & 63) + ((r5 & 64) ? 256 : 0);
    } else srccol = p;
    t[ty][tx] = W[(size_t)(kx + ty) * srcld + srccol];
    __syncthreads();
    int pp = py + ty, k = kx + tx;
    wdst[dsto + (size_t)pp * KDIM + k] = __float2half_rn(t[tx][ty]);
}

// ------------------------- fused LN + conv -> fp16 --------------------------
__global__ __launch_bounds__(256)
void lnconv_kernel(const float* __restrict__ h,
                   const float* __restrict__ g, const float* __restrict__ bta,
                   const float* __restrict__ w, const float* __restrict__ cbias,
                   __half* __restrict__ oh) {
    __shared__ float sh[36][DMODEL];
    int b = blockIdx.y;
    int t0 = blockIdx.x * 32;
    int warp = threadIdx.x >> 5, lane = threadIdx.x & 31;

    for (int r = warp; r < 36; r += 8) {
        int t = t0 - 2 + r;
        if (t < 0 || t >= TLEN) {
            float4 z = make_float4(0.f, 0.f, 0.f, 0.f);
            ((float4*)sh[r])[lane * 2]     = z;
            ((float4*)sh[r])[lane * 2 + 1] = z;
        } else {
            const float4* p = (const float4*)(h + ((size_t)(b * TLEN + t)) * DMODEL);
            float4 v0 = p[lane * 2], v1 = p[lane * 2 + 1];
            float s  = v0.x + v0.y + v0.z + v0.w + v1.x + v1.y + v1.z + v1.w;
            float sq = v0.x*v0.x + v0.y*v0.y + v0.z*v0.z + v0.w*v0.w
                     + v1.x*v1.x + v1.y*v1.y + v1.z*v1.z + v1.w*v1.w;
            #pragma unroll
            for (int o = 16; o > 0; o >>= 1) {
                s  += __shfl_xor_sync(0xffffffffu, s,  o);
                sq += __shfl_xor_sync(0xffffffffu, sq, o);
            }
            float mu  = s  * (1.0f / (float)DMODEL);
            float var = sq * (1.0f / (float)DMODEL) - mu * mu;
            float rs  = rsqrtf(var + EPSV);
            const float4* gp = (const float4*)g;
            const float4* bp = (const float4*)bta;
            float4 g0 = gp[lane * 2], g1 = gp[lane * 2 + 1];
            float4 b0 = bp[lane * 2], b1 = bp[lane * 2 + 1];
            float4 o0, o1;
            o0.x = (v0.x - mu) * rs * g0.x + b0.x;
            o0.y = (v0.y - mu) * rs * g0.y + b0.y;
            o0.z = (v0.z - mu) * rs * g0.z + b0.z;
            o0.w = (v0.w - mu) * rs * g0.w + b0.w;
            o1.x = (v1.x - mu) * rs * g1.x + b1.x;
            o1.y = (v1.y - mu) * rs * g1.y + b1.y;
            o1.z = (v1.z - mu) * rs * g1.z + b1.z;
            o1.w = (v1.w - mu) * rs * g1.w + b1.w;
            ((float4*)sh[r])[lane * 2]     = o0;
            ((float4*)sh[r])[lane * 2 + 1] = o1;
        }
    }
    __syncthreads();

    int d = threadIdx.x;
    float w0 = w[d * KSZ + 0], w1 = w[d * KSZ + 1], w2 = w[d * KSZ + 2];
    float w3 = w[d * KSZ + 3], w4 = w[d * KSZ + 4];
    float cb = cbias[d];
    float acc[32];
    #pragma unroll
    for (int t = 0; t < 32; t++) {
        float a = cb;
        a = fmaf(w0, sh[t    ][d], a);
        a = fmaf(w1, sh[t + 1][d], a);
        a = fmaf(w2, sh[t + 2][d], a);
        a = fmaf(w3, sh[t + 3][d], a);
        a = fmaf(w4, sh[t + 4][d], a);
        acc[t] = a;
    }
    __syncthreads();
    #pragma unroll
    for (int t = 0; t < 32; t++) sh[t][d] = acc[t];
    __syncthreads();

    size_t rowbase = (size_t)(b * TLEN + t0);
    for (int p = threadIdx.x; p < 32 * 128; p += 256) {
        int r = p >> 7, dp = (p & 127) * 2;
        __half2 ph;
        ph.x = __float2half_rn(sh[r][dp]);
        ph.y = __float2half_rn(sh[r][dp + 1]);
        *(__half2*)(oh + (rowbase + r) * DMODEL + dp) = ph;
    }
}

// ------------------------- warp-per-row final layer norm --------------------
__global__ void ln_warp_kernel(const float* __restrict__ in,
                               const float* __restrict__ g,
                               const float* __restrict__ bta,
                               float* __restrict__ out) {
    int warp = threadIdx.x >> 5, lane = threadIdx.x & 31;
    int m = blockIdx.x * 8 + warp;
    const float4* p = (const float4*)(in + (size_t)m * DMODEL);
    float4 v0 = p[lane * 2], v1 = p[lane * 2 + 1];
    float s  = v0.x + v0.y + v0.z + v0.w + v1.x + v1.y + v1.z + v1.w;
    float sq = v0.x*v0.x + v0.y*v0.y + v0.z*v0.z + v0.w*v0.w
             + v1.x*v1.x + v1.y*v1.y + v1.z*v1.z + v1.w*v1.w;
    #pragma unroll
    for (int o = 16; o > 0; o >>= 1) {
        s  += __shfl_xor_sync(0xffffffffu, s,  o);
        sq += __shfl_xor_sync(0xffffffffu, sq, o);
    }
    float mu  = s  * (1.0f / (float)DMODEL);
    float var = sq * (1.0f / (float)DMODEL) - mu * mu;
    float rs  = rsqrtf(var + EPSV);
    const float4* gp = (const float4*)g;
    const float4* bp = (const float4*)bta;
    float4 g0 = gp[lane * 2], g1 = gp[lane * 2 + 1];
    float4 b0 = bp[lane * 2], b1 = bp[lane * 2 + 1];
    float4 o0, o1;
    o0.x = (v0.x - mu) * rs * g0.x + b0.x;
    o0.y = (v0.y - mu) * rs * g0.y + b0.y;
    o0.z = (v0.z - mu) * rs * g0.z + b0.z;
    o0.w = (v0.w - mu) * rs * g0.w + b0.w;
    o1.x = (v1.x - mu) * rs * g1.x + b1.x;
    o1.y = (v1.y - mu) * rs * g1.y + b1.y;
    o1.z = (v1.z - mu) * rs * g1.z + b1.z;
    o1.w = (v1.w - mu) * rs * g1.w + b1.w;
    ((float4*)(out + (size_t)m * DMODEL))[lane * 2]     = o0;
    ((float4*)(out + (size_t)m * DMODEL))[lane * 2 + 1] = o1;
}

// ------------------------- fp16 mma.sync GEMM (64x128, 4-stage ring) --------
// Per CTA: D[64,128] = A[64,256] @ Bprep[128rows,256]^T, fp16 in, fp32 acc.
// MODE 0: outf = D + bias;  MODE 1: += resid;  MODE 2: gated sigmoid*gelu
// -> fp16 (gate = D cols 0-63, value = D cols 64-127).
// smem: 4 stages x {A:64rows, B:128rows} x 80 B rows = 61440 B.
#define TS4   80
#define A_T4  (64 * TS4)             // 5120
#define B_T4  (128 * TS4)            // 10240
#define ST4   (A_T4 + B_T4)          // 15360
#define GEMM_SMEM (4 * ST4)          // 61440

template<int MODE>
__global__ __launch_bounds__(256, 3)
void gemm_mma_kernel(const __half* __restrict__ A,
                     const __half* __restrict__ B,
                     const float* __restrict__ bias, const float* __restrict__ resid,
                     float* __restrict__ outf,
                     __half* __restrict__ outh) {
    extern __shared__ char sm[];
    unsigned sbase = smem_u32(sm);
    const int tid = threadIdx.x, wid = tid >> 5, lane = tid & 31;
    const int m0 = blockIdx.y * 64;
    const int nb = blockIdx.x;
    const int n0p = nb * 128;

    const char* A8 = (const char*)A + (size_t)m0 * 512;
    const char* B8 = (const char*)B + (size_t)n0p * 512;

    auto load_stage = [&](int s, int k0) {
        unsigned dst0 = sbase + s * ST4;
        int kbyte = k0 * 2;
        {   // A: 64 rows x 4 x 16B chunks = 256 = one pass
            int row = tid >> 2, c16 = (tid & 3) * 16;
            CP_ASYNC16(dst0 + row * TS4 + c16,
                       A8 + (size_t)row * 512 + kbyte + c16);
        }
        #pragma unroll
        for (int j = 0; j < 2; j++) {   // B: 128 rows x 4 chunks = 512
            int i = tid + j * 256;
            int row = i >> 2, c16 = (i & 3) * 16;
            CP_ASYNC16(dst0 + A_T4 + row * TS4 + c16,
                       B8 + (size_t)row * 512 + kbyte + c16);
        }
        CP_COMMIT();
    };

    load_stage(0, 0);
    load_stage(1, 32);
    load_stage(2, 64);

    const int warpM = wid & 1, warpN = wid >> 1;     // 2 x 4 warps, 32x32 tiles
    float acc[2][4][4];
    #pragma unroll
    for (int mt = 0; mt < 2; mt++)
        #pragma unroll
        for (int nt = 0; nt < 4; nt++)
            #pragma unroll
            for (int e = 0; e < 4; e++) acc[mt][nt][e] = 0.0f;

    const unsigned a_row = warpM * 32 + (lane & 15);
    const unsigned a_cofs = ((lane >> 4) << 3) * 2;          // 0 or 16 bytes
    const unsigned b_row = warpN * 32 + (lane & 7);
    const unsigned b_cofs = (((lane >> 3) & 1) << 3) * 2;    // 0 or 16 bytes

    #pragma unroll 1
    for (int i = 0; i < 8; i++) {
        if (i < 6) { CP_WAIT(2); } else if (i == 6) { CP_WAIT(1); } else { CP_WAIT(0); }
        __syncthreads();
        if (i + 3 < 8) load_stage((i + 3) & 3, (i + 3) * 32);
        unsigned st  = sbase + (i & 3) * ST4;
        unsigned ab  = st;
        unsigned bb  = st + A_T4;
        #pragma unroll
        for (int ks = 0; ks < 2; ks++) {
            unsigned aoff = a_row * TS4 + ks * 32 + a_cofs;
            unsigned boff = b_row * TS4 + ks * 32 + b_cofs;
            unsigned af[2][4];
            unsigned bf[4][2];
            ldsm_x4(af[0], ab + aoff);
            ldsm_x4(af[1], ab + aoff + 16 * TS4);
            #pragma unroll
            for (int nt = 0; nt < 4; nt++)
                ldsm_x2(bf[nt], bb + boff + nt * 8 * TS4);
            #pragma unroll
            for (int nt = 0; nt < 4; nt++)
                #pragma unroll
                for (int mt = 0; mt < 2; mt++)
                    mma16816h(acc[mt][nt], af[mt], bf[nt]);
        }
    }
    __syncthreads();   // all stages consumed; reuse smem for epilogue

    // ---- epilogue: stage D through smem (64 rows x 132-float stride) ----
    float* smf = (float*)sm;
    #pragma unroll
    for (int mt = 0; mt < 2; mt++) {
        #pragma unroll
        for (int nt = 0; nt < 4; nt++) {
            int r = warpM * 32 + mt * 16 + (lane >> 2);
            int c = warpN * 32 + nt * 8 + (lane & 3) * 2;
            smf[r * 132 + c]           = acc[mt][nt][0];
            smf[r * 132 + c + 1]       = acc[mt][nt][1];
            smf[(r + 8) * 132 + c]     = acc[mt][nt][2];
            smf[(r + 8) * 132 + c + 1] = acc[mt][nt][3];
        }
    }
    __syncthreads();

    if (MODE == 2) {
        const int outn0 = nb * 64;
        for (int i = tid; i < 64 * 32; i += 256) {
            int row = i >> 5, c2 = (i & 31) * 2;
            float gg0 = smf[row * 132 + c2]     + bias[outn0 + c2];
            float gg1 = smf[row * 132 + c2 + 1] + bias[outn0 + c2 + 1];
            float vv0 = smf[row * 132 + 64 + c2]     + bias[256 + outn0 + c2];
            float vv1 = smf[row * 132 + 64 + c2 + 1] + bias[256 + outn0 + c2 + 1];
            float s0 = 1.0f / (1.0f + expf(-gg0));
            float s1 = 1.0f / (1.0f + expf(-gg1));
            float e0 = 0.5f * vv0 * (1.0f + erff(vv0 * 0.7071067811865476f));
            float e1 = 0.5f * vv1 * (1.0f + erff(vv1 * 0.7071067811865476f));
            __half2 ph;
            ph.x = __float2half_rn(s0 * e0);
            ph.y = __float2half_rn(s1 * e1);
            size_t ob = (size_t)(m0 + row) * DMODEL + outn0 + c2;
            *(__half2*)(outh + ob) = ph;
        }
    } else {
        for (int i = tid; i < 64 * 32; i += 256) {
            int row = i >> 5, c4 = (i & 31) * 4;
            float4 o;
            o.x = smf[row * 132 + c4]     + bias[n0p + c4];
            o.y = smf[row * 132 + c4 + 1] + bias[n0p + c4 + 1];
            o.z = smf[row * 132 + c4 + 2] + bias[n0p + c4 + 2];
            o.w = smf[row * 132 + c4 + 3] + bias[n0p + c4 + 3];
            size_t base = (size_t)(m0 + row) * DMODEL + n0p + c4;
            if (MODE == 1) {
                float4 rr = *(const float4*)(resid + base);
                o.x += rr.x; o.y += rr.y; o.z += rr.z; o.w += rr.w;
            }
            *(float4*)(outf + base) = o;
        }
    }
}

// ------------------------- mask tail ----------------------------------------
__global__ void fill_ones_kernel(float* __restrict__ p, int n) {
    int i = blockIdx.x * blockDim.x + threadIdx.x;
    if (i < n) p[i] = 1.0f;
}

// ---------------------------------------------------------------------------
extern "C" void kernel_launch(void* const* d_in, const int* in_sizes, int n_in,
                              void* d_out, int out_size) {
    const float* x      = (const float*)d_in[0];
    const void*  mask   = d_in[1];
    const float* in_w   = (const float*)d_in[2];
    const float* in_b   = (const float*)d_in[3];
    const float* ln_g   = (const float*)d_in[4];
    const float* ln_b   = (const float*)d_in[5];
    const float* dw_w   = (const float*)d_in[6];
    const float* dw_b   = (const float*)d_in[7];
    const float* win_w  = (const float*)d_in[8];
    const float* win_b  = (const float*)d_in[9];
    const float* wout_w = (const float*)d_in[10];
    const float* wout_b = (const float*)d_in[11];
    const float* fn_g   = (const float*)d_in[12];
    const float* fn_b   = (const float*)d_in[13];
    float* out = (float*)d_out;

    __half *a, *c, *w;
    float *h;
    cudaGetSymbolAddress((void**)&a, g_a);
    cudaGetSymbolAddress((void**)&c, g_c);
    cudaGetSymbolAddress((void**)&w, g_w);
    cudaGetSymbolAddress((void**)&h, g_h);

    cudaFuncSetAttribute(gemm_mma_kernel<0>,
        cudaFuncAttributeMaxDynamicSharedMemorySize, GEMM_SMEM);
    cudaFuncSetAttribute(gemm_mma_kernel<1>,
        cudaFuncAttributeMaxDynamicSharedMemorySize, GEMM_SMEM);
    cudaFuncSetAttribute(gemm_mma_kernel<2>,
        cudaFuncAttributeMaxDynamicSharedMemorySize, GEMM_SMEM);

    // 1) mask dtype detection + lengths (one launch)
    lengths_kernel<<<BATCH, 256>>>((const unsigned char*)mask);

    // 2) fused weight prep (one launch: 64 + 4*64 + 4*128 = 832 blocks)
    prep_all_w_kernel<<<832, dim3(32, 32)>>>(in_w, wout_w, win_w, w);

    // 3) compress to fp16
    compress_kernel<<<dim3(TLEN / 2, BATCH), 128>>>(x);

    // 4) input projection: h = xc @ in_w + in_b   (grid 2 x 128 = 256 CTAs)
    gemm_mma_kernel<0><<<dim3(2, 128), 256, GEMM_SMEM>>>(
        a, w + WOFF_IN, in_b, nullptr, h, nullptr);

    // 5) conv blocks
    for (int i = 0; i < NBLK; i++) {
        lnconv_kernel<<<dim3(TLEN / 32, BATCH), 256>>>(
            h, ln_g + i * DMODEL, ln_b + i * DMODEL,
            dw_w + (size_t)i * DMODEL * KSZ, dw_b + i * DMODEL, a);
        gemm_mma_kernel<2><<<dim3(4, 128), 256, GEMM_SMEM>>>(
            a, w + WOFF_GATE(i), win_b + (size_t)i * 2 * DMODEL, nullptr,
            nullptr, c);
        gemm_mma_kernel<1><<<dim3(2, 128), 256, GEMM_SMEM>>>(
            c, w + WOFF_WOUT(i), wout_b + i * DMODEL, h, h, nullptr);
    }

    // 6) final layer norm -> out
    ln_warp_kernel<<<MROWS / 8, 256>>>(h, fn_g, fn_b, out);

    // 7) comp_mask tail (all True -> 1.0f) if present in out buffer
    int main_elems = MROWS * DMODEL;
    int extra = out_size - main_elems;
    if (extra > 0)
        fill_ones_kernel<<<(extra + 255) / 256, 256>>>(out + main_elems, extra);
}